// round 5
// baseline (speedup 1.0000x reference)
#include <cuda_runtime.h>
#include <cuda_fp16.h>
#include <cstdint>

#define BB      8
#define NODES   1600
#define VD      256
#define FD      256
#define KCH     32             // K chunk (mma)
#define NCH     (NODES / KCH)  // 50
#define STAGE_B 30720
#define SMEM_DYN (2 * STAGE_B)

#define G1R     16             // gemm1 rows per CTA
#define XSP     260            // xs row pad (16B-aligned rows)
#define SMEM_G1 ((G1R * XSP + 32 * 257) * 4)

#define SR      16             // soft rows per CTA
#define SMEM_SF ((BB * NODES + SR * 50 + BB * SR * 2) * 4)

// ---------------- scratch (device globals; allocation-free) ----------------
__device__ float                 g_Wh1 [BB * NODES];
__device__ float                 g_Wh2 [BB * NODES];
__device__ float                 g_il  [BB * NODES];
__device__ __align__(128) __half g_WhT_hi[BB * FD * NODES];
__device__ __align__(128) __half g_WhT_lo[BB * FD * NODES];
__device__ __align__(128) __half g_P_hi[(size_t)BB * NODES * NODES];
__device__ __align__(128) __half g_P_lo[(size_t)BB * NODES * NODES];

// ---------------- PTX helpers (sm_80-era only) ----------------
__device__ __forceinline__ uint32_t smem_u32(const void* p) {
    uint32_t a;
    asm("{ .reg .u64 t; cvta.to.shared.u64 t, %1; cvt.u32.u64 %0, t; }" : "=r"(a) : "l"(p));
    return a;
}
__device__ __forceinline__ void cp16(uint32_t dst, const void* src) {
    asm volatile("cp.async.cg.shared.global [%0], [%1], 16;" :: "r"(dst), "l"(src) : "memory");
}
#define CP_COMMIT() asm volatile("cp.async.commit_group;" ::: "memory")
#define CP_WAIT1()  asm volatile("cp.async.wait_group 1;" ::: "memory")
#define CP_WAIT0()  asm volatile("cp.async.wait_group 0;" ::: "memory")

__device__ __forceinline__ void ldmx4(uint32_t* r, uint32_t addr) {
    asm volatile("ldmatrix.sync.aligned.m8n8.x4.shared.b16 {%0,%1,%2,%3}, [%4];"
                 : "=r"(r[0]), "=r"(r[1]), "=r"(r[2]), "=r"(r[3]) : "r"(addr));
}
__device__ __forceinline__ void mma16816(float* c, const uint32_t* a,
                                         uint32_t b0, uint32_t b1) {
    asm volatile(
        "mma.sync.aligned.m16n8k16.row.col.f32.f16.f16.f32 "
        "{%0,%1,%2,%3}, {%4,%5,%6,%7}, {%8,%9}, {%0,%1,%2,%3};"
        : "+f"(c[0]), "+f"(c[1]), "+f"(c[2]), "+f"(c[3])
        : "r"(a[0]), "r"(a[1]), "r"(a[2]), "r"(a[3]), "r"(b0), "r"(b1));
}

// ---------------------------------------------------------------------------
// Kernel 1 (fused): Wh tile -> (a) Wh1/Wh2 projections, (b) WhT hi/lo split.
// CTA = 16 rows x 256 f. g_Wh is never materialized.
// ---------------------------------------------------------------------------
__global__ __launch_bounds__(256) void k_gemm1f(const float* __restrict__ x,
                                                const float* __restrict__ W,
                                                const float* __restrict__ bW,
                                                const float* __restrict__ ai,
                                                const float* __restrict__ bi,
                                                const float* __restrict__ aj,
                                                const float* __restrict__ bj) {
    extern __shared__ __align__(16) float dsm1[];
    float (*xs)[XSP]  = (float(*)[XSP])dsm1;               // [16][260]
    float (*WsT)[257] = (float(*)[257])(dsm1 + G1R * XSP); // [32][257]

    const int f   = threadIdx.x;
    const int blk = blockIdx.x;                 // 800
    const long m0 = (long)blk * G1R;            // global row (= b*1600 + n0)
    const int b   = blk / 100;
    const int n0  = (blk % 100) * G1R;

    for (int r = 0; r < G1R; r++)
        xs[r][f] = x[(m0 + r) * VD + f];

    float acc[G1R];
#pragma unroll
    for (int r = 0; r < G1R; r++) acc[r] = 0.f;
    const float bv = bW[f];
    const int kk = f & 31, fg0 = f >> 5;

    for (int v0 = 0; v0 < VD; v0 += 32) {
        __syncthreads();
#pragma unroll
        for (int p = 0; p < 32; p++) {
            int fg = fg0 + p * 8;
            WsT[kk][fg] = W[fg * VD + v0 + kk];
        }
        __syncthreads();
        float wreg[32];
#pragma unroll
        for (int k = 0; k < 32; k++) wreg[k] = WsT[k][f];
#pragma unroll
        for (int r = 0; r < G1R; r++) {
#pragma unroll
            for (int k4 = 0; k4 < 8; k4++) {
                float4 xv = *(const float4*)&xs[r][v0 + k4 * 4];
                acc[r] += xv.x * wreg[k4 * 4 + 0];
                acc[r] += xv.y * wreg[k4 * 4 + 1];
                acc[r] += xv.z * wreg[k4 * 4 + 2];
                acc[r] += xv.w * wreg[k4 * 4 + 3];
            }
        }
    }

    // ---- stage result tile in smem (reuse xs) ----
    __syncthreads();
#pragma unroll
    for (int r = 0; r < G1R; r++) xs[r][f] = acc[r] + bv;
    __syncthreads();

    // ---- fused projections: rows 2w, 2w+1 per warp ----
    const int warp = f >> 5, lane = f & 31;
#pragma unroll
    for (int rr = 0; rr < 2; rr++) {
        const int r = 2 * warp + rr;
        float s1 = 0.f, s2 = 0.f;
#pragma unroll
        for (int q = 0; q < 8; q++) {
            float v = xs[r][lane + 32 * q];
            s1 += v * ai[lane + 32 * q];
            s2 += v * aj[lane + 32 * q];
        }
#pragma unroll
        for (int o = 16; o; o >>= 1) {
            s1 += __shfl_xor_sync(0xFFFFFFFFu, s1, o);
            s2 += __shfl_xor_sync(0xFFFFFFFFu, s2, o);
        }
        if (lane == 0) {
            g_Wh1[m0 + r] = s1 + bi[0];
            g_Wh2[m0 + r] = s2 + bj[0];
        }
    }

    // ---- fused transpose + fp16 hi/lo split: WhT[b][f][n0..n0+16) ----
    const int jp = f & 7;        // j pair 0..7 (j = 2jp, 2jp+1)
    const int fs = f >> 3;       // 0..31
#pragma unroll
    for (int p = 0; p < 8; p++) {
        const int ff = 32 * p + fs;
        float v0 = xs[2 * jp][ff];
        float v1 = xs[2 * jp + 1][ff];
        __half h0 = __float2half_rn(v0);
        __half h1 = __float2half_rn(v1);
        __half l0 = __float2half_rn(v0 - __half2float(h0));
        __half l1 = __float2half_rn(v1 - __half2float(h1));
        size_t o = ((size_t)(b * FD + ff)) * NODES + n0 + 2 * jp;
        *(__half2*)&g_WhT_hi[o] = __halves2half2(h0, h1);
        *(__half2*)&g_WhT_lo[o] = __halves2half2(l0, l1);
    }
}

// ---------------------------------------------------------------------------
// Kernel 2: masked softmax (all 8 batches per CTA; adj read ONCE as bitmask).
// Stores UNNORMALIZED exp(s-m) as fp16 hi/lo; 1/sum to g_il.
// Monotonicity: row max = leaky(Wh1_i + max_masked Wh2_j).
// ---------------------------------------------------------------------------
__global__ __launch_bounds__(256) void k_soft(const int* __restrict__ adj) {
    extern __shared__ __align__(16) float dsm2[];
    float*    wh2s = dsm2;                                   // [8][1600]
    uint32_t* bm   = (uint32_t*)(dsm2 + BB * NODES);         // [16][50]
    float*    wh1s = dsm2 + BB * NODES + SR * 50;            // [8][16]
    float*    mrow = wh1s + BB * SR;                         // [8][16]

    const int tid = threadIdx.x;
    const int i0  = blockIdx.x * SR;
    const int warp = tid >> 5, lane = tid & 31;

    for (int t = tid; t < BB * NODES; t += 256) {
        int b = t / NODES, j = t - b * NODES;
        wh2s[t] = g_Wh2[b * NODES + j];
    }
    if (tid < BB * SR) {
        int b = tid >> 4, r = tid & 15;
        wh1s[tid] = g_Wh1[b * NODES + i0 + r];
    }
    __syncthreads();

    // ---- pass B: adj bitmask + per-batch masked max of Wh2 ----
#pragma unroll
    for (int rr = 0; rr < 2; rr++) {
        const int r = warp + rr * 8;
        const int* arow = adj + (size_t)(i0 + r) * NODES;
        float mx[BB];
#pragma unroll
        for (int q = 0; q < BB; q++) mx[q] = -3e38f;
        for (int w = 0; w < 50; w++) {
            int a = arow[w * 32 + lane];
            uint32_t bit = __ballot_sync(0xFFFFFFFFu, a > 0);
            if (lane == 0) bm[r * 50 + w] = bit;
            if (a > 0) {
#pragma unroll
                for (int q = 0; q < BB; q++)
                    mx[q] = fmaxf(mx[q], wh2s[q * NODES + w * 32 + lane]);
            }
        }
#pragma unroll
        for (int q = 0; q < BB; q++) {
            float v = mx[q];
#pragma unroll
            for (int o = 16; o; o >>= 1) v = fmaxf(v, __shfl_xor_sync(0xFFFFFFFFu, v, o));
            if (lane == 0) mrow[q * SR + r] = v;
        }
    }
    __syncthreads();

    // ---- pass C: one warp per batch, all 16 rows; write exp + sum ----
    const int b = warp;
    for (int r = 0; r < SR; r++) {
        const float wh1 = wh1s[b * SR + r];
        const float M   = mrow[b * SR + r];
        float em = wh1 + M;
        em = em > 0.f ? em : 0.2f * em;
        const float m = (M > -1e30f) ? em : -1e9f;
        const size_t pb = ((size_t)(b * NODES + i0 + r)) * NODES;
        float sum = 0.f;
#pragma unroll 5
        for (int it = 0; it < 25; it++) {
            const int j = it * 64 + 2 * lane;
            const uint32_t word = bm[r * 50 + (j >> 5)];
            const int a0 = (word >> (j & 31)) & 1;
            const int a1 = (word >> ((j & 31) + 1)) & 1;
            float2 w2 = *(const float2*)&wh2s[b * NODES + j];
            float e0 = wh1 + w2.x; e0 = e0 > 0.f ? e0 : 0.2f * e0;
            float e1 = wh1 + w2.y; e1 = e1 > 0.f ? e1 : 0.2f * e1;
            float s0 = a0 ? e0 : -1e9f;
            float s1 = a1 ? e1 : -1e9f;
            float x0 = __expf(s0 - m);
            float x1 = __expf(s1 - m);
            sum += x0 + x1;
            __half h0 = __float2half_rn(x0);
            __half h1 = __float2half_rn(x1);
            __half l0 = __float2half_rn(x0 - __half2float(h0));
            __half l1 = __float2half_rn(x1 - __half2float(h1));
            *(__half2*)&g_P_hi[pb + j] = __halves2half2(h0, h1);
            *(__half2*)&g_P_lo[pb + j] = __halves2half2(l0, l1);
        }
#pragma unroll
        for (int o = 16; o; o >>= 1) sum += __shfl_xor_sync(0xFFFFFFFFu, sum, o);
        if (lane == 0) g_il[b * NODES + i0 + r] = 1.f / sum;
    }
}

// ---------------------------------------------------------------------------
// Kernel 3: h_hat = P @ Wh^T (mma.sync fp16 hi/lo, 3 terms), row-scale by il,
// then ELU. CTA 64x128, 8 warps, K=32 chunks, double-buffered cp.async.
// ---------------------------------------------------------------------------
__global__ __launch_bounds__(256) void k_mma2(float* __restrict__ out) {
    extern __shared__ __align__(128) char dsm[];
    const int tid = threadIdx.x, wid = tid >> 5, lane = tid & 31;
    const int m0 = blockIdx.x * 64, n0 = blockIdx.y * 128, b = blockIdx.z;
    const int wm = wid >> 2, wn = wid & 3;

    const __half* Ah = g_P_hi + ((size_t)(b * NODES + m0)) * NODES;
    const __half* Al = g_P_lo + ((size_t)(b * NODES + m0)) * NODES;
    const __half* Bh = g_WhT_hi + ((size_t)b * FD + n0) * NODES;
    const __half* Bl = g_WhT_lo + ((size_t)b * FD + n0) * NODES;

    const uint32_t s0 = smem_u32(dsm);

    auto load_chunk = [&](int c) {
        const uint32_t st = s0 + (c & 1) * STAGE_B;
        const int jt = c * KCH;
        {
            int row = tid >> 2, cc = tid & 3;
            uint32_t o = (uint32_t)(row * 80 + cc * 16);
            const size_t go = (size_t)row * NODES + jt + cc * 8;
            cp16(st + o,        Ah + go);
            cp16(st + 5120 + o, Al + go);
        }
        for (int t = tid; t < 512; t += 256) {
            int row = t >> 2, cc = t & 3;
            uint32_t o = (uint32_t)(row * 80 + cc * 16);
            const size_t go = (size_t)row * NODES + jt + cc * 8;
            cp16(st + 10240 + o, Bh + go);
            cp16(st + 20480 + o, Bl + go);
        }
        CP_COMMIT();
    };

    float acc[2][4][4];
#pragma unroll
    for (int mt = 0; mt < 2; mt++)
#pragma unroll
        for (int nt = 0; nt < 4; nt++)
#pragma unroll
            for (int q = 0; q < 4; q++) acc[mt][nt][q] = 0.f;

    const int aRow = wm * 32 + (lane & 7) + ((lane >> 3) & 1) * 8;
    const int aC16 = ((lane >> 4) & 1) * 16;
    const int bRow = wn * 32 + (lane & 7) + ((lane >> 4) & 1) * 8;
    const int bC16 = ((lane >> 3) & 1) * 16;

    load_chunk(0);

    for (int c = 0; c < NCH; c++) {
        if (c + 1 < NCH) { load_chunk(c + 1); CP_WAIT1(); }
        else            { CP_WAIT0(); }
        __syncthreads();

        const uint32_t st = s0 + (c & 1) * STAGE_B;
#pragma unroll
        for (int ks = 0; ks < 2; ks++) {
            const int koff = ks * 32;
            uint32_t ah[2][4], al[2][4], bh[2][4], bl[2][4];
#pragma unroll
            for (int mt = 0; mt < 2; mt++) {
                uint32_t ao = st + (uint32_t)((aRow + mt * 16) * 80 + aC16 + koff);
                ldmx4(ah[mt], ao);
                ldmx4(al[mt], ao + 5120);
            }
#pragma unroll
            for (int p = 0; p < 2; p++) {
                uint32_t bo = st + 10240 +
                              (uint32_t)((bRow + p * 16) * 80 + bC16 + koff);
                ldmx4(bh[p], bo);
                ldmx4(bl[p], bo + 10240);
            }
#pragma unroll
            for (int mt = 0; mt < 2; mt++) {
#pragma unroll
                for (int nt = 0; nt < 4; nt++) {
                    const int p = nt >> 1, hf = (nt & 1) * 2;
                    mma16816(acc[mt][nt], ah[mt], bh[p][hf], bh[p][hf + 1]);
                    mma16816(acc[mt][nt], ah[mt], bl[p][hf], bl[p][hf + 1]);
                    mma16816(acc[mt][nt], al[mt], bh[p][hf], bh[p][hf + 1]);
                }
            }
        }
        __syncthreads();
    }

    // ---- epilogue: deferred softmax scale (il), ELU, store ----
#pragma unroll
    for (int mt = 0; mt < 2; mt++) {
        const int mA = m0 + wm * 32 + mt * 16 + (lane >> 2);
        const float ilA = g_il[(size_t)b * NODES + mA];
        const float ilB = g_il[(size_t)b * NODES + mA + 8];
#pragma unroll
        for (int nt = 0; nt < 4; nt++) {
            const int n = n0 + wn * 32 + nt * 8 + (lane & 3) * 2;
            float* op = out + ((size_t)(b * NODES) + mA) * FD + n;
            float d0 = acc[mt][nt][0] * ilA, d1 = acc[mt][nt][1] * ilA;
            float d2 = acc[mt][nt][2] * ilB, d3 = acc[mt][nt][3] * ilB;
            float2 v0, v1;
            v0.x = d0 > 0.f ? d0 : (__expf(d0) - 1.f);
            v0.y = d1 > 0.f ? d1 : (__expf(d1) - 1.f);
            v1.x = d2 > 0.f ? d2 : (__expf(d2) - 1.f);
            v1.y = d3 > 0.f ? d3 : (__expf(d3) - 1.f);
            *(float2*)op = v0;
            *(float2*)(op + 8 * FD) = v1;
        }
    }
}

// ---------------------------------------------------------------------------
extern "C" void kernel_launch(void* const* d_in, const int* in_sizes, int n_in,
                              void* d_out, int out_size) {
    const float* h   = (const float*)d_in[0];
    const int*   adj = (const int*)  d_in[1];
    const float* W   = (const float*)d_in[2];
    const float* bW  = (const float*)d_in[3];
    const float* ai  = (const float*)d_in[4];
    const float* bi  = (const float*)d_in[5];
    const float* aj  = (const float*)d_in[6];
    const float* bj  = (const float*)d_in[7];
    float* out = (float*)d_out;

    cudaFuncSetAttribute(k_gemm1f, cudaFuncAttributeMaxDynamicSharedMemorySize, SMEM_G1);
    cudaFuncSetAttribute(k_soft,   cudaFuncAttributeMaxDynamicSharedMemorySize, SMEM_SF);
    cudaFuncSetAttribute(k_mma2,   cudaFuncAttributeMaxDynamicSharedMemorySize, SMEM_DYN);

    k_gemm1f<<<(BB * NODES) / G1R, 256, SMEM_G1>>>(h, W, bW, ai, bi, aj, bj);
    k_soft<<<NODES / SR, 256, SMEM_SF>>>(adj);
    dim3 gm(NODES / 64, FD / 128, BB);
    k_mma2<<<gm, 256, SMEM_DYN>>>(out);
}

// round 6
// speedup vs baseline: 1.1080x; 1.1080x over previous
#include <cuda_runtime.h>
#include <cuda_fp16.h>
#include <cstdint>

#define BB      8
#define NODES   1600
#define VD      256
#define FD      256
#define MTOT    (BB * NODES)   // 12800
#define KCH     32
#define NCH     (NODES / KCH)  // 50  (k_mma2)
#define NCHG    (VD / KCH)     // 8   (k_g1mma)
#define STAGE_B 30720
#define SMEM_DYN (2 * STAGE_B)

// ---------------- scratch (device globals; allocation-free) ----------------
__device__ float                 g_Wh1 [MTOT];
__device__ float                 g_Wh2 [MTOT];
__device__ float                 g_il  [MTOT];
__device__ float                 g_ui[VD], g_uj[VD];
__device__ float                 g_ci, g_cj;
__device__ __align__(128) __half g_xh[(size_t)MTOT * VD];
__device__ __align__(128) __half g_xl[(size_t)MTOT * VD];
__device__ __align__(128) __half g_W16h[FD * VD];
__device__ __align__(128) __half g_W16l[FD * VD];
__device__ __align__(128) __half g_WhT_hi[BB * FD * NODES];
__device__ __align__(128) __half g_WhT_lo[BB * FD * NODES];
__device__ __align__(128) __half g_P_hi[(size_t)BB * NODES * NODES];
__device__ __align__(128) __half g_P_lo[(size_t)BB * NODES * NODES];

// ---------------- PTX helpers (sm_80-era only) ----------------
__device__ __forceinline__ uint32_t smem_u32(const void* p) {
    uint32_t a;
    asm("{ .reg .u64 t; cvta.to.shared.u64 t, %1; cvt.u32.u64 %0, t; }" : "=r"(a) : "l"(p));
    return a;
}
__device__ __forceinline__ void cp16(uint32_t dst, const void* src) {
    asm volatile("cp.async.cg.shared.global [%0], [%1], 16;" :: "r"(dst), "l"(src) : "memory");
}
#define CP_COMMIT() asm volatile("cp.async.commit_group;" ::: "memory")
#define CP_WAIT1()  asm volatile("cp.async.wait_group 1;" ::: "memory")
#define CP_WAIT0()  asm volatile("cp.async.wait_group 0;" ::: "memory")

__device__ __forceinline__ void ldmx4(uint32_t* r, uint32_t addr) {
    asm volatile("ldmatrix.sync.aligned.m8n8.x4.shared.b16 {%0,%1,%2,%3}, [%4];"
                 : "=r"(r[0]), "=r"(r[1]), "=r"(r[2]), "=r"(r[3]) : "r"(addr));
}
__device__ __forceinline__ void mma16816(float* c, const uint32_t* a,
                                         uint32_t b0, uint32_t b1) {
    asm volatile(
        "mma.sync.aligned.m16n8k16.row.col.f32.f16.f16.f32 "
        "{%0,%1,%2,%3}, {%4,%5,%6,%7}, {%8,%9}, {%0,%1,%2,%3};"
        : "+f"(c[0]), "+f"(c[1]), "+f"(c[2]), "+f"(c[3])
        : "r"(a[0]), "r"(a[1]), "r"(a[2]), "r"(a[3]), "r"(b0), "r"(b1));
}
__device__ __forceinline__ void split2(float v0, float v1, __half2& h, __half2& l) {
    __half h0 = __float2half_rn(v0), h1 = __float2half_rn(v1);
    h = __halves2half2(h0, h1);
    l = __halves2half2(__float2half_rn(v0 - __half2float(h0)),
                       __float2half_rn(v1 - __half2float(h1)));
}

// ---------------------------------------------------------------------------
// k_split_x: x fp32 -> xh/xl fp16 split (vectorized)
// ---------------------------------------------------------------------------
__global__ __launch_bounds__(256) void k_split_x(const float4* __restrict__ x) {
    const size_t idx = (size_t)blockIdx.x * 256 + threadIdx.x;  // 819200 float4s
    float4 v = x[idx];
    __half2 h01, l01, h23, l23;
    split2(v.x, v.y, h01, l01);
    split2(v.z, v.w, h23, l23);
    __half2* ph = (__half2*)&g_xh[idx * 4];
    __half2* pl = (__half2*)&g_xl[idx * 4];
    ph[0] = h01; ph[1] = h23;
    pl[0] = l01; pl[1] = l23;
}

// ---------------------------------------------------------------------------
// k_wprep: u_i = W^T ai, u_j = W^T aj, c_i/c_j scalars; W -> fp16 split.
// One CTA, 256 threads.
// ---------------------------------------------------------------------------
__global__ __launch_bounds__(256) void k_wprep(const float* __restrict__ W,
                                               const float* __restrict__ bW,
                                               const float* __restrict__ ai,
                                               const float* __restrict__ bi,
                                               const float* __restrict__ aj,
                                               const float* __restrict__ bj) {
    __shared__ float red[16];
    const int v = threadIdx.x;
    float ui = 0.f, uj = 0.f;
    for (int f = 0; f < FD; f++) {
        float w = W[f * VD + v];
        ui += ai[f] * w;
        uj += aj[f] * w;
    }
    g_ui[v] = ui;
    g_uj[v] = uj;

    // split W
    for (int t = v; t < FD * VD / 2; t += 256) {
        float2 w2 = ((const float2*)W)[t];
        __half2 h, l;
        split2(w2.x, w2.y, h, l);
        *(__half2*)&g_W16h[2 * t] = h;
        *(__half2*)&g_W16l[2 * t] = l;
    }

    // c_i = ai.bW + bi ; c_j = aj.bW + bj
    float p1 = ai[v] * bW[v];
    float p2 = aj[v] * bW[v];
    const int warp = v >> 5, lane = v & 31;
#pragma unroll
    for (int o = 16; o; o >>= 1) {
        p1 += __shfl_xor_sync(0xFFFFFFFFu, p1, o);
        p2 += __shfl_xor_sync(0xFFFFFFFFu, p2, o);
    }
    if (lane == 0) { red[warp] = p1; red[8 + warp] = p2; }
    __syncthreads();
    if (v == 0) {
        float c1 = bi[0], c2 = bj[0];
        for (int w = 0; w < 8; w++) { c1 += red[w]; c2 += red[8 + w]; }
        g_ci = c1; g_cj = c2;
    }
}

// ---------------------------------------------------------------------------
// k_projx: Wh1[m] = x[m,:].u_i + c_i ; Wh2 likewise (warp per row, on x)
// ---------------------------------------------------------------------------
__global__ __launch_bounds__(256) void k_projx(const float* __restrict__ x) {
    const int gwarp = (blockIdx.x * blockDim.x + threadIdx.x) >> 5;  // 12800
    const int lane = threadIdx.x & 31;
    const float* row = x + (size_t)gwarp * VD;
    float s1 = 0.f, s2 = 0.f;
#pragma unroll
    for (int q = 0; q < 8; q++) {
        const int k = lane + 32 * q;
        float v = row[k];
        s1 += v * g_ui[k];
        s2 += v * g_uj[k];
    }
#pragma unroll
    for (int o = 16; o; o >>= 1) {
        s1 += __shfl_xor_sync(0xFFFFFFFFu, s1, o);
        s2 += __shfl_xor_sync(0xFFFFFFFFu, s2, o);
    }
    if (lane == 0) {
        g_Wh1[gwarp] = s1 + g_ci;
        g_Wh2[gwarp] = s2 + g_cj;
    }
}

// ---------------------------------------------------------------------------
// k_g1mma: Wh = x @ W^T (+bW) on tensor cores, epilogue writes WhT hi/lo.
// CTA 64(M) x 128(N), grid (200, 2). K = 256 in 8 chunks.
// ---------------------------------------------------------------------------
__global__ __launch_bounds__(256) void k_g1mma(const float* __restrict__ bW) {
    extern __shared__ __align__(128) char dsm[];
    __shared__ float bWs[128];
    const int tid = threadIdx.x, wid = tid >> 5, lane = tid & 31;
    const int m0 = blockIdx.x * 64, n0 = blockIdx.y * 128;
    const int wm = wid >> 2, wn = wid & 3;

    if (tid < 128) bWs[tid] = bW[n0 + tid];

    const __half* Ah = g_xh + (size_t)m0 * VD;
    const __half* Al = g_xl + (size_t)m0 * VD;
    const __half* Bh = g_W16h + (size_t)n0 * VD;
    const __half* Bl = g_W16l + (size_t)n0 * VD;

    const uint32_t s0 = smem_u32(dsm);

    auto load_chunk = [&](int c) {
        const uint32_t st = s0 + (c & 1) * STAGE_B;
        const int jt = c * KCH;
        {
            int row = tid >> 2, cc = tid & 3;
            uint32_t o = (uint32_t)(row * 80 + cc * 16);
            const size_t go = (size_t)row * VD + jt + cc * 8;
            cp16(st + o,        Ah + go);
            cp16(st + 5120 + o, Al + go);
        }
        for (int t = tid; t < 512; t += 256) {
            int row = t >> 2, cc = t & 3;
            uint32_t o = (uint32_t)(row * 80 + cc * 16);
            const size_t go = (size_t)row * VD + jt + cc * 8;
            cp16(st + 10240 + o, Bh + go);
            cp16(st + 20480 + o, Bl + go);
        }
        CP_COMMIT();
    };

    float acc[2][4][4];
#pragma unroll
    for (int mt = 0; mt < 2; mt++)
#pragma unroll
        for (int nt = 0; nt < 4; nt++)
#pragma unroll
            for (int q = 0; q < 4; q++) acc[mt][nt][q] = 0.f;

    const int aRow = wm * 32 + (lane & 7) + ((lane >> 3) & 1) * 8;
    const int aC16 = ((lane >> 4) & 1) * 16;
    const int bRow = wn * 32 + (lane & 7) + ((lane >> 4) & 1) * 8;
    const int bC16 = ((lane >> 3) & 1) * 16;

    load_chunk(0);

    for (int c = 0; c < NCHG; c++) {
        if (c + 1 < NCHG) { load_chunk(c + 1); CP_WAIT1(); }
        else             { CP_WAIT0(); }
        __syncthreads();
        const uint32_t st = s0 + (c & 1) * STAGE_B;
#pragma unroll
        for (int ks = 0; ks < 2; ks++) {
            const int koff = ks * 32;
            uint32_t ah[2][4], al[2][4], bh[2][4], bl[2][4];
#pragma unroll
            for (int mt = 0; mt < 2; mt++) {
                uint32_t ao = st + (uint32_t)((aRow + mt * 16) * 80 + aC16 + koff);
                ldmx4(ah[mt], ao);
                ldmx4(al[mt], ao + 5120);
            }
#pragma unroll
            for (int p = 0; p < 2; p++) {
                uint32_t bo = st + 10240 +
                              (uint32_t)((bRow + p * 16) * 80 + bC16 + koff);
                ldmx4(bh[p], bo);
                ldmx4(bl[p], bo + 10240);
            }
#pragma unroll
            for (int mt = 0; mt < 2; mt++) {
#pragma unroll
                for (int nt = 0; nt < 4; nt++) {
                    const int p = nt >> 1, hf = (nt & 1) * 2;
                    mma16816(acc[mt][nt], ah[mt], bh[p][hf], bh[p][hf + 1]);
                    mma16816(acc[mt][nt], ah[mt], bl[p][hf], bl[p][hf + 1]);
                    mma16816(acc[mt][nt], al[mt], bh[p][hf], bh[p][hf + 1]);
                }
            }
        }
        __syncthreads();
    }

    // ---- stage 64x128 fp32 tile in smem, then transposed hi/lo write ----
    float* s = (float*)dsm;   // [64][129]
#pragma unroll
    for (int mt = 0; mt < 2; mt++) {
        const int ml = wm * 32 + mt * 16 + (lane >> 2);
#pragma unroll
        for (int nt = 0; nt < 4; nt++) {
            const int nl = wn * 32 + nt * 8 + (lane & 3) * 2;
            s[ml * 129 + nl]           = acc[mt][nt][0];
            s[ml * 129 + nl + 1]       = acc[mt][nt][1];
            s[(ml + 8) * 129 + nl]     = acc[mt][nt][2];
            s[(ml + 8) * 129 + nl + 1] = acc[mt][nt][3];
        }
    }
    __syncthreads();

    const int b  = m0 / NODES;
    const int j0 = m0 % NODES;
#pragma unroll
    for (int it = 0; it < 16; it++) {
        const int f = wid * 16 + it;
        const float bw = bWs[f];
        float v0 = s[(2 * lane) * 129 + f] + bw;
        float v1 = s[(2 * lane + 1) * 129 + f] + bw;
        __half2 h, l;
        split2(v0, v1, h, l);
        size_t o = ((size_t)(b * FD + n0 + f)) * NODES + j0 + 2 * lane;
        *(__half2*)&g_WhT_hi[o] = h;
        *(__half2*)&g_WhT_lo[o] = l;
    }
}

// ---------------------------------------------------------------------------
// k_soft: grid (50, 8). 32 rows x 1 batch per CTA. 2 passes:
//   pass1: adj -> ballot bitmask + masked max of Wh2 (monotonic-max trick)
//   pass2: unnormalized exp -> P hi/lo, sum -> g_il (norm deferred to k_mma2)
// ---------------------------------------------------------------------------
__global__ __launch_bounds__(256) void k_soft(const int* __restrict__ adj) {
    __shared__ float Wh2s[NODES];
    __shared__ float Wh1s[32], ms[32];
    __shared__ uint32_t bm[32][50];
    const int tid = threadIdx.x, b = blockIdx.y;
    const int i0 = blockIdx.x * 32;
    const int warp = tid >> 5, lane = tid & 31;

    for (int j = tid; j < NODES; j += 256)
        Wh2s[j] = g_Wh2[b * NODES + j];
    if (tid < 32)
        Wh1s[tid] = g_Wh1[b * NODES + i0 + tid];
    __syncthreads();

#pragma unroll
    for (int rr = 0; rr < 4; rr++) {
        const int r = warp * 4 + rr;
        const int* arow = adj + (size_t)(i0 + r) * NODES;
        float mx = -3e38f;
        for (int w = 0; w < 50; w++) {
            int a = arow[w * 32 + lane];
            uint32_t bit = __ballot_sync(0xFFFFFFFFu, a > 0);
            if (lane == 0) bm[r][w] = bit;
            if (a > 0) mx = fmaxf(mx, Wh2s[w * 32 + lane]);
        }
#pragma unroll
        for (int o = 16; o; o >>= 1) mx = fmaxf(mx, __shfl_xor_sync(0xFFFFFFFFu, mx, o));
        if (lane == 0) {
            float em = Wh1s[r] + mx;
            em = em > 0.f ? em : 0.2f * em;
            ms[r] = (mx > -1e30f) ? em : -1e9f;
        }
    }
    __syncthreads();

#pragma unroll
    for (int rr = 0; rr < 4; rr++) {
        const int r = warp * 4 + rr;
        const float wh1 = Wh1s[r], m = ms[r];
        const size_t pb = ((size_t)(b * NODES + i0 + r)) * NODES;
        float sum = 0.f;
#pragma unroll 5
        for (int it = 0; it < 25; it++) {
            const int j = it * 64 + 2 * lane;
            const uint32_t word = bm[r][j >> 5];
            const int a0 = (word >> (j & 31)) & 1;
            const int a1 = (word >> ((j & 31) + 1)) & 1;
            float2 w2 = *(const float2*)&Wh2s[j];
            float e0 = wh1 + w2.x; e0 = e0 > 0.f ? e0 : 0.2f * e0;
            float e1 = wh1 + w2.y; e1 = e1 > 0.f ? e1 : 0.2f * e1;
            float x0 = __expf((a0 ? e0 : -1e9f) - m);
            float x1 = __expf((a1 ? e1 : -1e9f) - m);
            sum += x0 + x1;
            __half2 h, l;
            split2(x0, x1, h, l);
            *(__half2*)&g_P_hi[pb + j] = h;
            *(__half2*)&g_P_lo[pb + j] = l;
        }
#pragma unroll
        for (int o = 16; o; o >>= 1) sum += __shfl_xor_sync(0xFFFFFFFFu, sum, o);
        if (lane == 0) g_il[b * NODES + i0 + r] = 1.f / sum;
    }
}

// ---------------------------------------------------------------------------
// k_mma2: h_hat = P @ Wh^T (fp16 hi/lo, 3 terms), il scale + ELU epilogue.
// ---------------------------------------------------------------------------
__global__ __launch_bounds__(256) void k_mma2(float* __restrict__ out) {
    extern __shared__ __align__(128) char dsm[];
    const int tid = threadIdx.x, wid = tid >> 5, lane = tid & 31;
    const int m0 = blockIdx.x * 64, n0 = blockIdx.y * 128, b = blockIdx.z;
    const int wm = wid >> 2, wn = wid & 3;

    const __half* Ah = g_P_hi + ((size_t)(b * NODES + m0)) * NODES;
    const __half* Al = g_P_lo + ((size_t)(b * NODES + m0)) * NODES;
    const __half* Bh = g_WhT_hi + ((size_t)b * FD + n0) * NODES;
    const __half* Bl = g_WhT_lo + ((size_t)b * FD + n0) * NODES;

    const uint32_t s0 = smem_u32(dsm);

    auto load_chunk = [&](int c) {
        const uint32_t st = s0 + (c & 1) * STAGE_B;
        const int jt = c * KCH;
        {
            int row = tid >> 2, cc = tid & 3;
            uint32_t o = (uint32_t)(row * 80 + cc * 16);
            const size_t go = (size_t)row * NODES + jt + cc * 8;
            cp16(st + o,        Ah + go);
            cp16(st + 5120 + o, Al + go);
        }
        for (int t = tid; t < 512; t += 256) {
            int row = t >> 2, cc = t & 3;
            uint32_t o = (uint32_t)(row * 80 + cc * 16);
            const size_t go = (size_t)row * NODES + jt + cc * 8;
            cp16(st + 10240 + o, Bh + go);
            cp16(st + 20480 + o, Bl + go);
        }
        CP_COMMIT();
    };

    float acc[2][4][4];
#pragma unroll
    for (int mt = 0; mt < 2; mt++)
#pragma unroll
        for (int nt = 0; nt < 4; nt++)
#pragma unroll
            for (int q = 0; q < 4; q++) acc[mt][nt][q] = 0.f;

    const int aRow = wm * 32 + (lane & 7) + ((lane >> 3) & 1) * 8;
    const int aC16 = ((lane >> 4) & 1) * 16;
    const int bRow = wn * 32 + (lane & 7) + ((lane >> 4) & 1) * 8;
    const int bC16 = ((lane >> 3) & 1) * 16;

    load_chunk(0);

    for (int c = 0; c < NCH; c++) {
        if (c + 1 < NCH) { load_chunk(c + 1); CP_WAIT1(); }
        else            { CP_WAIT0(); }
        __syncthreads();
        const uint32_t st = s0 + (c & 1) * STAGE_B;
#pragma unroll
        for (int ks = 0; ks < 2; ks++) {
            const int koff = ks * 32;
            uint32_t ah[2][4], al[2][4], bh[2][4], bl[2][4];
#pragma unroll
            for (int mt = 0; mt < 2; mt++) {
                uint32_t ao = st + (uint32_t)((aRow + mt * 16) * 80 + aC16 + koff);
                ldmx4(ah[mt], ao);
                ldmx4(al[mt], ao + 5120);
            }
#pragma unroll
            for (int p = 0; p < 2; p++) {
                uint32_t bo = st + 10240 +
                              (uint32_t)((bRow + p * 16) * 80 + bC16 + koff);
                ldmx4(bh[p], bo);
                ldmx4(bl[p], bo + 10240);
            }
#pragma unroll
            for (int mt = 0; mt < 2; mt++) {
#pragma unroll
                for (int nt = 0; nt < 4; nt++) {
                    const int p = nt >> 1, hf = (nt & 1) * 2;
                    mma16816(acc[mt][nt], ah[mt], bh[p][hf], bh[p][hf + 1]);
                    mma16816(acc[mt][nt], ah[mt], bl[p][hf], bl[p][hf + 1]);
                    mma16816(acc[mt][nt], al[mt], bh[p][hf], bh[p][hf + 1]);
                }
            }
        }
        __syncthreads();
    }

#pragma unroll
    for (int mt = 0; mt < 2; mt++) {
        const int mA = m0 + wm * 32 + mt * 16 + (lane >> 2);
        const float ilA = g_il[(size_t)b * NODES + mA];
        const float ilB = g_il[(size_t)b * NODES + mA + 8];
#pragma unroll
        for (int nt = 0; nt < 4; nt++) {
            const int n = n0 + wn * 32 + nt * 8 + (lane & 3) * 2;
            float* op = out + ((size_t)(b * NODES) + mA) * FD + n;
            float d0 = acc[mt][nt][0] * ilA, d1 = acc[mt][nt][1] * ilA;
            float d2 = acc[mt][nt][2] * ilB, d3 = acc[mt][nt][3] * ilB;
            float2 v0, v1;
            v0.x = d0 > 0.f ? d0 : (__expf(d0) - 1.f);
            v0.y = d1 > 0.f ? d1 : (__expf(d1) - 1.f);
            v1.x = d2 > 0.f ? d2 : (__expf(d2) - 1.f);
            v1.y = d3 > 0.f ? d3 : (__expf(d3) - 1.f);
            *(float2*)op = v0;
            *(float2*)(op + 8 * FD) = v1;
        }
    }
}

// ---------------------------------------------------------------------------
extern "C" void kernel_launch(void* const* d_in, const int* in_sizes, int n_in,
                              void* d_out, int out_size) {
    const float* h   = (const float*)d_in[0];
    const int*   adj = (const int*)  d_in[1];
    const float* W   = (const float*)d_in[2];
    const float* bW  = (const float*)d_in[3];
    const float* ai  = (const float*)d_in[4];
    const float* bi  = (const float*)d_in[5];
    const float* aj  = (const float*)d_in[6];
    const float* bj  = (const float*)d_in[7];
    float* out = (float*)d_out;

    cudaFuncSetAttribute(k_g1mma, cudaFuncAttributeMaxDynamicSharedMemorySize, SMEM_DYN);
    cudaFuncSetAttribute(k_mma2,  cudaFuncAttributeMaxDynamicSharedMemorySize, SMEM_DYN);

    k_split_x<<<(MTOT * VD / 4) / 256, 256>>>((const float4*)h);
    k_wprep<<<1, 256>>>(W, bW, ai, bi, aj, bj);
    k_projx<<<MTOT / 8, 256>>>(h);
    k_soft<<<dim3(NODES / 32, BB), 256>>>(adj);
    k_g1mma<<<dim3(MTOT / 64, 2), 256, SMEM_DYN>>>(bW);
    dim3 gm(NODES / 64, FD / 128, BB);
    k_mma2<<<gm, 256, SMEM_DYN>>>(out);
}

// round 7
// speedup vs baseline: 1.3779x; 1.2436x over previous
#include <cuda_runtime.h>
#include <cuda_fp16.h>
#include <cstdint>

#define BB      8
#define NODES   1600
#define VD      256
#define FD      256
#define MTOT    (BB * NODES)   // 12800
#define KCH     32
#define NCH     (NODES / KCH)  // 50  (k_mma2)
#define NCHG    (VD / KCH)     // 8   (k_g1mma)
// k_g1mma stages (A hi/lo + B hi/lo)
#define STAGE_G 30720
#define SMEM_G  (2 * STAGE_G)
// k_mma2 stages (A hi only + B hi/lo)
#define STAGE_M 25600
#define SMEM_M  (2 * STAGE_M)

// ---------------- scratch (device globals; allocation-free) ----------------
__device__ float                 g_Wh1 [MTOT];
__device__ float                 g_Wh2 [MTOT];
__device__ float                 g_il  [MTOT];
__device__ float                 g_ui[VD], g_uj[VD];
__device__ float                 g_ci, g_cj;
__device__ __align__(128) __half g_xh[(size_t)MTOT * VD];
__device__ __align__(128) __half g_xl[(size_t)MTOT * VD];
__device__ __align__(128) __half g_W16h[FD * VD];
__device__ __align__(128) __half g_W16l[FD * VD];
__device__ __align__(128) __half g_WhT_hi[BB * FD * NODES];
__device__ __align__(128) __half g_WhT_lo[BB * FD * NODES];
__device__ __align__(128) __half g_P_hi[(size_t)BB * NODES * NODES];

// ---------------- PTX helpers (sm_80-era only) ----------------
__device__ __forceinline__ uint32_t smem_u32(const void* p) {
    uint32_t a;
    asm("{ .reg .u64 t; cvta.to.shared.u64 t, %1; cvt.u32.u64 %0, t; }" : "=r"(a) : "l"(p));
    return a;
}
__device__ __forceinline__ void cp16(uint32_t dst, const void* src) {
    asm volatile("cp.async.cg.shared.global [%0], [%1], 16;" :: "r"(dst), "l"(src) : "memory");
}
#define CP_COMMIT() asm volatile("cp.async.commit_group;" ::: "memory")
#define CP_WAIT1()  asm volatile("cp.async.wait_group 1;" ::: "memory")
#define CP_WAIT0()  asm volatile("cp.async.wait_group 0;" ::: "memory")

__device__ __forceinline__ void ldmx4(uint32_t* r, uint32_t addr) {
    asm volatile("ldmatrix.sync.aligned.m8n8.x4.shared.b16 {%0,%1,%2,%3}, [%4];"
                 : "=r"(r[0]), "=r"(r[1]), "=r"(r[2]), "=r"(r[3]) : "r"(addr));
}
__device__ __forceinline__ void mma16816(float* c, const uint32_t* a,
                                         uint32_t b0, uint32_t b1) {
    asm volatile(
        "mma.sync.aligned.m16n8k16.row.col.f32.f16.f16.f32 "
        "{%0,%1,%2,%3}, {%4,%5,%6,%7}, {%8,%9}, {%0,%1,%2,%3};"
        : "+f"(c[0]), "+f"(c[1]), "+f"(c[2]), "+f"(c[3])
        : "r"(a[0]), "r"(a[1]), "r"(a[2]), "r"(a[3]), "r"(b0), "r"(b1));
}
__device__ __forceinline__ void split2(float v0, float v1, __half2& h, __half2& l) {
    __half h0 = __float2half_rn(v0), h1 = __float2half_rn(v1);
    h = __halves2half2(h0, h1);
    l = __halves2half2(__float2half_rn(v0 - __half2float(h0)),
                       __float2half_rn(v1 - __half2float(h1)));
}

// ---------------------------------------------------------------------------
// k_split_x: x fp32 -> xh/xl fp16 split (vectorized)
// ---------------------------------------------------------------------------
__global__ __launch_bounds__(256) void k_split_x(const float4* __restrict__ x) {
    const size_t idx = (size_t)blockIdx.x * 256 + threadIdx.x;
    float4 v = x[idx];
    __half2 h01, l01, h23, l23;
    split2(v.x, v.y, h01, l01);
    split2(v.z, v.w, h23, l23);
    __half2* ph = (__half2*)&g_xh[idx * 4];
    __half2* pl = (__half2*)&g_xl[idx * 4];
    ph[0] = h01; ph[1] = h23;
    pl[0] = l01; pl[1] = l23;
}

// ---------------------------------------------------------------------------
// k_wprep: u_i = W^T ai, u_j = W^T aj, c_i/c_j; W -> fp16 split. One CTA.
// ---------------------------------------------------------------------------
__global__ __launch_bounds__(256) void k_wprep(const float* __restrict__ W,
                                               const float* __restrict__ bW,
                                               const float* __restrict__ ai,
                                               const float* __restrict__ bi,
                                               const float* __restrict__ aj,
                                               const float* __restrict__ bj) {
    __shared__ float red[16];
    const int v = threadIdx.x;
    float ui = 0.f, uj = 0.f;
    for (int f = 0; f < FD; f++) {
        float w = W[f * VD + v];
        ui += ai[f] * w;
        uj += aj[f] * w;
    }
    g_ui[v] = ui;
    g_uj[v] = uj;

    for (int t = v; t < FD * VD / 2; t += 256) {
        float2 w2 = ((const float2*)W)[t];
        __half2 h, l;
        split2(w2.x, w2.y, h, l);
        *(__half2*)&g_W16h[2 * t] = h;
        *(__half2*)&g_W16l[2 * t] = l;
    }

    float p1 = ai[v] * bW[v];
    float p2 = aj[v] * bW[v];
    const int warp = v >> 5, lane = v & 31;
#pragma unroll
    for (int o = 16; o; o >>= 1) {
        p1 += __shfl_xor_sync(0xFFFFFFFFu, p1, o);
        p2 += __shfl_xor_sync(0xFFFFFFFFu, p2, o);
    }
    if (lane == 0) { red[warp] = p1; red[8 + warp] = p2; }
    __syncthreads();
    if (v == 0) {
        float c1 = bi[0], c2 = bj[0];
        for (int w = 0; w < 8; w++) { c1 += red[w]; c2 += red[8 + w]; }
        g_ci = c1; g_cj = c2;
    }
}

// ---------------------------------------------------------------------------
// k_projx: Wh1/Wh2 directly from x (warp per row)
// ---------------------------------------------------------------------------
__global__ __launch_bounds__(256) void k_projx(const float* __restrict__ x) {
    const int gwarp = (blockIdx.x * blockDim.x + threadIdx.x) >> 5;
    const int lane = threadIdx.x & 31;
    const float* row = x + (size_t)gwarp * VD;
    float s1 = 0.f, s2 = 0.f;
#pragma unroll
    for (int q = 0; q < 8; q++) {
        const int k = lane + 32 * q;
        float v = row[k];
        s1 += v * g_ui[k];
        s2 += v * g_uj[k];
    }
#pragma unroll
    for (int o = 16; o; o >>= 1) {
        s1 += __shfl_xor_sync(0xFFFFFFFFu, s1, o);
        s2 += __shfl_xor_sync(0xFFFFFFFFu, s2, o);
    }
    if (lane == 0) {
        g_Wh1[gwarp] = s1 + g_ci;
        g_Wh2[gwarp] = s2 + g_cj;
    }
}

// ---------------------------------------------------------------------------
// k_g1mma: Wh = x @ W^T (+bW), 3-term fp16 hi/lo; epilogue -> WhT hi/lo.
// ---------------------------------------------------------------------------
__global__ __launch_bounds__(256) void k_g1mma(const float* __restrict__ bW) {
    extern __shared__ __align__(128) char dsm[];
    __shared__ float bWs[128];
    const int tid = threadIdx.x, wid = tid >> 5, lane = tid & 31;
    const int m0 = blockIdx.x * 64, n0 = blockIdx.y * 128;
    const int wm = wid >> 2, wn = wid & 3;

    if (tid < 128) bWs[tid] = bW[n0 + tid];

    const __half* Ah = g_xh + (size_t)m0 * VD;
    const __half* Al = g_xl + (size_t)m0 * VD;
    const __half* Bh = g_W16h + (size_t)n0 * VD;
    const __half* Bl = g_W16l + (size_t)n0 * VD;

    const uint32_t s0 = smem_u32(dsm);

    auto load_chunk = [&](int c) {
        const uint32_t st = s0 + (c & 1) * STAGE_G;
        const int jt = c * KCH;
        {
            int row = tid >> 2, cc = tid & 3;
            uint32_t o = (uint32_t)(row * 80 + cc * 16);
            const size_t go = (size_t)row * VD + jt + cc * 8;
            cp16(st + o,        Ah + go);
            cp16(st + 5120 + o, Al + go);
        }
        for (int t = tid; t < 512; t += 256) {
            int row = t >> 2, cc = t & 3;
            uint32_t o = (uint32_t)(row * 80 + cc * 16);
            const size_t go = (size_t)row * VD + jt + cc * 8;
            cp16(st + 10240 + o, Bh + go);
            cp16(st + 20480 + o, Bl + go);
        }
        CP_COMMIT();
    };

    float acc[2][4][4];
#pragma unroll
    for (int mt = 0; mt < 2; mt++)
#pragma unroll
        for (int nt = 0; nt < 4; nt++)
#pragma unroll
            for (int q = 0; q < 4; q++) acc[mt][nt][q] = 0.f;

    const int aRow = wm * 32 + (lane & 7) + ((lane >> 3) & 1) * 8;
    const int aC16 = ((lane >> 4) & 1) * 16;
    const int bRow = wn * 32 + (lane & 7) + ((lane >> 4) & 1) * 8;
    const int bC16 = ((lane >> 3) & 1) * 16;

    load_chunk(0);

    for (int c = 0; c < NCHG; c++) {
        if (c + 1 < NCHG) { load_chunk(c + 1); CP_WAIT1(); }
        else             { CP_WAIT0(); }
        __syncthreads();
        const uint32_t st = s0 + (c & 1) * STAGE_G;
#pragma unroll
        for (int ks = 0; ks < 2; ks++) {
            const int koff = ks * 32;
            uint32_t ah[2][4], al[2][4], bh[2][4], bl[2][4];
#pragma unroll
            for (int mt = 0; mt < 2; mt++) {
                uint32_t ao = st + (uint32_t)((aRow + mt * 16) * 80 + aC16 + koff);
                ldmx4(ah[mt], ao);
                ldmx4(al[mt], ao + 5120);
            }
#pragma unroll
            for (int p = 0; p < 2; p++) {
                uint32_t bo = st + 10240 +
                              (uint32_t)((bRow + p * 16) * 80 + bC16 + koff);
                ldmx4(bh[p], bo);
                ldmx4(bl[p], bo + 10240);
            }
#pragma unroll
            for (int mt = 0; mt < 2; mt++) {
#pragma unroll
                for (int nt = 0; nt < 4; nt++) {
                    const int p = nt >> 1, hf = (nt & 1) * 2;
                    mma16816(acc[mt][nt], ah[mt], bh[p][hf], bh[p][hf + 1]);
                    mma16816(acc[mt][nt], ah[mt], bl[p][hf], bl[p][hf + 1]);
                    mma16816(acc[mt][nt], al[mt], bh[p][hf], bh[p][hf + 1]);
                }
            }
        }
        __syncthreads();
    }

    float* s = (float*)dsm;   // [64][129]
#pragma unroll
    for (int mt = 0; mt < 2; mt++) {
        const int ml = wm * 32 + mt * 16 + (lane >> 2);
#pragma unroll
        for (int nt = 0; nt < 4; nt++) {
            const int nl = wn * 32 + nt * 8 + (lane & 3) * 2;
            s[ml * 129 + nl]           = acc[mt][nt][0];
            s[ml * 129 + nl + 1]       = acc[mt][nt][1];
            s[(ml + 8) * 129 + nl]     = acc[mt][nt][2];
            s[(ml + 8) * 129 + nl + 1] = acc[mt][nt][3];
        }
    }
    __syncthreads();

    const int b  = m0 / NODES;
    const int j0 = m0 % NODES;
#pragma unroll
    for (int it = 0; it < 16; it++) {
        const int f = wid * 16 + it;
        const float bw = bWs[f];
        float v0 = s[(2 * lane) * 129 + f] + bw;
        float v1 = s[(2 * lane + 1) * 129 + f] + bw;
        __half2 h, l;
        split2(v0, v1, h, l);
        size_t o = ((size_t)(b * FD + n0 + f)) * NODES + j0 + 2 * lane;
        *(__half2*)&g_WhT_hi[o] = h;
        *(__half2*)&g_WhT_lo[o] = l;
    }
}

// ---------------------------------------------------------------------------
// k_soft: grid (100, 8), 16 rows/CTA. 2 passes (monotonic max, ballot bitmask,
// unnormalized exp as SINGLE fp16; 1/sum -> g_il; norm deferred to k_mma2).
// ---------------------------------------------------------------------------
__global__ __launch_bounds__(256) void k_soft(const int* __restrict__ adj) {
    __shared__ float Wh2s[NODES];
    __shared__ float Wh1s[16], ms[16];
    __shared__ uint32_t bm[16][50];
    const int tid = threadIdx.x, b = blockIdx.y;
    const int i0 = blockIdx.x * 16;
    const int warp = tid >> 5, lane = tid & 31;

    for (int j = tid; j < NODES; j += 256)
        Wh2s[j] = g_Wh2[b * NODES + j];
    if (tid < 16)
        Wh1s[tid] = g_Wh1[b * NODES + i0 + tid];
    __syncthreads();

#pragma unroll
    for (int rr = 0; rr < 2; rr++) {
        const int r = warp * 2 + rr;
        const int* arow = adj + (size_t)(i0 + r) * NODES;
        float mx = -3e38f;
        for (int w = 0; w < 50; w++) {
            int a = arow[w * 32 + lane];
            uint32_t bit = __ballot_sync(0xFFFFFFFFu, a > 0);
            if (lane == 0) bm[r][w] = bit;
            if (a > 0) mx = fmaxf(mx, Wh2s[w * 32 + lane]);
        }
#pragma unroll
        for (int o = 16; o; o >>= 1) mx = fmaxf(mx, __shfl_xor_sync(0xFFFFFFFFu, mx, o));
        if (lane == 0) {
            float em = Wh1s[r] + mx;
            em = em > 0.f ? em : 0.2f * em;
            ms[r] = (mx > -1e30f) ? em : -1e9f;
        }
    }
    __syncthreads();

#pragma unroll
    for (int rr = 0; rr < 2; rr++) {
        const int r = warp * 2 + rr;
        const float wh1 = Wh1s[r], m = ms[r];
        const size_t pb = ((size_t)(b * NODES + i0 + r)) * NODES;
        float sum = 0.f;
#pragma unroll 5
        for (int it = 0; it < 25; it++) {
            const int j = it * 64 + 2 * lane;
            const uint32_t word = bm[r][j >> 5];
            const int a0 = (word >> (j & 31)) & 1;
            const int a1 = (word >> ((j & 31) + 1)) & 1;
            float2 w2 = *(const float2*)&Wh2s[j];
            float e0 = wh1 + w2.x; e0 = e0 > 0.f ? e0 : 0.2f * e0;
            float e1 = wh1 + w2.y; e1 = e1 > 0.f ? e1 : 0.2f * e1;
            float x0 = __expf((a0 ? e0 : -1e9f) - m);
            float x1 = __expf((a1 ? e1 : -1e9f) - m);
            sum += x0 + x1;
            *(__half2*)&g_P_hi[pb + j] =
                __halves2half2(__float2half_rn(x0), __float2half_rn(x1));
        }
#pragma unroll
        for (int o = 16; o; o >>= 1) sum += __shfl_xor_sync(0xFFFFFFFFu, sum, o);
        if (lane == 0) g_il[b * NODES + i0 + r] = 1.f / sum;
    }
}

// ---------------------------------------------------------------------------
// k_mma2: h_hat = P(fp16) @ Wh^T(hi/lo) — 2 terms; il scale + ELU epilogue.
// Stage: A 5120 | Bh 10240 @5120 | Bl 10240 @15360  (25600 B)
// ---------------------------------------------------------------------------
__global__ __launch_bounds__(256) void k_mma2(float* __restrict__ out) {
    extern __shared__ __align__(128) char dsm[];
    const int tid = threadIdx.x, wid = tid >> 5, lane = tid & 31;
    const int m0 = blockIdx.x * 64, n0 = blockIdx.y * 128, b = blockIdx.z;
    const int wm = wid >> 2, wn = wid & 3;

    const __half* Ah = g_P_hi + ((size_t)(b * NODES + m0)) * NODES;
    const __half* Bh = g_WhT_hi + ((size_t)b * FD + n0) * NODES;
    const __half* Bl = g_WhT_lo + ((size_t)b * FD + n0) * NODES;

    const uint32_t s0 = smem_u32(dsm);

    auto load_chunk = [&](int c) {
        const uint32_t st = s0 + (c & 1) * STAGE_M;
        const int jt = c * KCH;
        {
            int row = tid >> 2, cc = tid & 3;
            uint32_t o = (uint32_t)(row * 80 + cc * 16);
            cp16(st + o, Ah + (size_t)row * NODES + jt + cc * 8);
        }
        for (int t = tid; t < 512; t += 256) {
            int row = t >> 2, cc = t & 3;
            uint32_t o = (uint32_t)(row * 80 + cc * 16);
            const size_t go = (size_t)row * NODES + jt + cc * 8;
            cp16(st + 5120 + o,  Bh + go);
            cp16(st + 15360 + o, Bl + go);
        }
        CP_COMMIT();
    };

    float acc[2][4][4];
#pragma unroll
    for (int mt = 0; mt < 2; mt++)
#pragma unroll
        for (int nt = 0; nt < 4; nt++)
#pragma unroll
            for (int q = 0; q < 4; q++) acc[mt][nt][q] = 0.f;

    const int aRow = wm * 32 + (lane & 7) + ((lane >> 3) & 1) * 8;
    const int aC16 = ((lane >> 4) & 1) * 16;
    const int bRow = wn * 32 + (lane & 7) + ((lane >> 4) & 1) * 8;
    const int bC16 = ((lane >> 3) & 1) * 16;

    load_chunk(0);

    for (int c = 0; c < NCH; c++) {
        if (c + 1 < NCH) { load_chunk(c + 1); CP_WAIT1(); }
        else            { CP_WAIT0(); }
        __syncthreads();
        const uint32_t st = s0 + (c & 1) * STAGE_M;
#pragma unroll
        for (int ks = 0; ks < 2; ks++) {
            const int koff = ks * 32;
            uint32_t ah[2][4], bh[2][4], bl[2][4];
#pragma unroll
            for (int mt = 0; mt < 2; mt++) {
                uint32_t ao = st + (uint32_t)((aRow + mt * 16) * 80 + aC16 + koff);
                ldmx4(ah[mt], ao);
            }
#pragma unroll
            for (int p = 0; p < 2; p++) {
                uint32_t bo = st + 5120 +
                              (uint32_t)((bRow + p * 16) * 80 + bC16 + koff);
                ldmx4(bh[p], bo);
                ldmx4(bl[p], bo + 10240);
            }
#pragma unroll
            for (int mt = 0; mt < 2; mt++) {
#pragma unroll
                for (int nt = 0; nt < 4; nt++) {
                    const int p = nt >> 1, hf = (nt & 1) * 2;
                    mma16816(acc[mt][nt], ah[mt], bh[p][hf], bh[p][hf + 1]);
                    mma16816(acc[mt][nt], ah[mt], bl[p][hf], bl[p][hf + 1]);
                }
            }
        }
        __syncthreads();
    }

#pragma unroll
    for (int mt = 0; mt < 2; mt++) {
        const int mA = m0 + wm * 32 + mt * 16 + (lane >> 2);
        const float ilA = g_il[(size_t)b * NODES + mA];
        const float ilB = g_il[(size_t)b * NODES + mA + 8];
#pragma unroll
        for (int nt = 0; nt < 4; nt++) {
            const int n = n0 + wn * 32 + nt * 8 + (lane & 3) * 2;
            float* op = out + ((size_t)(b * NODES) + mA) * FD + n;
            float d0 = acc[mt][nt][0] * ilA, d1 = acc[mt][nt][1] * ilA;
            float d2 = acc[mt][nt][2] * ilB, d3 = acc[mt][nt][3] * ilB;
            float2 v0, v1;
            v0.x = d0 > 0.f ? d0 : (__expf(d0) - 1.f);
            v0.y = d1 > 0.f ? d1 : (__expf(d1) - 1.f);
            v1.x = d2 > 0.f ? d2 : (__expf(d2) - 1.f);
            v1.y = d3 > 0.f ? d3 : (__expf(d3) - 1.f);
            *(float2*)op = v0;
            *(float2*)(op + 8 * FD) = v1;
        }
    }
}

// ---------------------------------------------------------------------------
extern "C" void kernel_launch(void* const* d_in, const int* in_sizes, int n_in,
                              void* d_out, int out_size) {
    const float* h   = (const float*)d_in[0];
    const int*   adj = (const int*)  d_in[1];
    const float* W   = (const float*)d_in[2];
    const float* bW  = (const float*)d_in[3];
    const float* ai  = (const float*)d_in[4];
    const float* bi  = (const float*)d_in[5];
    const float* aj  = (const float*)d_in[6];
    const float* bj  = (const float*)d_in[7];
    float* out = (float*)d_out;

    cudaFuncSetAttribute(k_g1mma, cudaFuncAttributeMaxDynamicSharedMemorySize, SMEM_G);
    cudaFuncSetAttribute(k_mma2,  cudaFuncAttributeMaxDynamicSharedMemorySize, SMEM_M);

    k_split_x<<<(MTOT * VD / 4) / 256, 256>>>((const float4*)h);
    k_wprep<<<1, 256>>>(W, bW, ai, bi, aj, bj);
    k_projx<<<MTOT / 8, 256>>>(h);
    k_soft<<<dim3(NODES / 16, BB), 256>>>(adj);
    k_g1mma<<<dim3(MTOT / 64, 2), 256, SMEM_G>>>(bW);
    dim3 gm(NODES / 64, FD / 128, BB);
    k_mma2<<<gm, 256, SMEM_M>>>(out);
}

// round 8
// speedup vs baseline: 1.4364x; 1.0424x over previous
#include <cuda_runtime.h>
#include <cuda_fp16.h>
#include <cstdint>

#define BB      8
#define NODES   1600
#define VD      256
#define FD      256
#define MTOT    (BB * NODES)   // 12800
#define KCH     32
#define NCH     (NODES / KCH)  // 50  (k_mma2f)
#define NCHG    (VD / KCH)     // 8   (k_g1mma)
// k_g1mma stages (A hi/lo + B hi/lo)
#define STAGE_G 30720
#define SMEM_G  (2 * STAGE_G)
// k_mma2f smem layout (bytes from base):
//   Wh2s 6400 | wh1s 256 | ms 256 | bm 12800 | A0 5120 | A1 5120 | B0 20480 | B1 20480
#define ABASE   19712
#define BBASE   (ABASE + 2 * 5120)      // 29952
#define SMEM_M  (BBASE + 2 * 20480)     // 70912

// ---------------- scratch (device globals; allocation-free) ----------------
__device__ float                 g_Wh1 [MTOT];
__device__ float                 g_Wh2 [MTOT];
__device__ float                 g_ui[VD], g_uj[VD];
__device__ float                 g_ci, g_cj;
__device__ uint32_t              g_bm[NODES * 50];
__device__ __align__(128) __half g_xh[(size_t)MTOT * VD];
__device__ __align__(128) __half g_xl[(size_t)MTOT * VD];
__device__ __align__(128) __half g_W16h[FD * VD];
__device__ __align__(128) __half g_W16l[FD * VD];
__device__ __align__(128) __half g_WhT_hi[BB * FD * NODES];
__device__ __align__(128) __half g_WhT_lo[BB * FD * NODES];

// ---------------- PTX helpers (sm_80-era only) ----------------
__device__ __forceinline__ uint32_t smem_u32(const void* p) {
    uint32_t a;
    asm("{ .reg .u64 t; cvta.to.shared.u64 t, %1; cvt.u32.u64 %0, t; }" : "=r"(a) : "l"(p));
    return a;
}
__device__ __forceinline__ void cp16(uint32_t dst, const void* src) {
    asm volatile("cp.async.cg.shared.global [%0], [%1], 16;" :: "r"(dst), "l"(src) : "memory");
}
#define CP_COMMIT() asm volatile("cp.async.commit_group;" ::: "memory")
#define CP_WAIT1()  asm volatile("cp.async.wait_group 1;" ::: "memory")
#define CP_WAIT0()  asm volatile("cp.async.wait_group 0;" ::: "memory")

__device__ __forceinline__ void ldmx4(uint32_t* r, uint32_t addr) {
    asm volatile("ldmatrix.sync.aligned.m8n8.x4.shared.b16 {%0,%1,%2,%3}, [%4];"
                 : "=r"(r[0]), "=r"(r[1]), "=r"(r[2]), "=r"(r[3]) : "r"(addr));
}
__device__ __forceinline__ void mma16816(float* c, const uint32_t* a,
                                         uint32_t b0, uint32_t b1) {
    asm volatile(
        "mma.sync.aligned.m16n8k16.row.col.f32.f16.f16.f32 "
        "{%0,%1,%2,%3}, {%4,%5,%6,%7}, {%8,%9}, {%0,%1,%2,%3};"
        : "+f"(c[0]), "+f"(c[1]), "+f"(c[2]), "+f"(c[3])
        : "r"(a[0]), "r"(a[1]), "r"(a[2]), "r"(a[3]), "r"(b0), "r"(b1));
}
__device__ __forceinline__ void split2(float v0, float v1, __half2& h, __half2& l) {
    __half h0 = __float2half_rn(v0), h1 = __float2half_rn(v1);
    h = __halves2half2(h0, h1);
    l = __halves2half2(__float2half_rn(v0 - __half2float(h0)),
                       __float2half_rn(v1 - __half2float(h1)));
}

// ---------------------------------------------------------------------------
// k_split_x: x fp32 -> xh/xl fp16 split
// ---------------------------------------------------------------------------
__global__ __launch_bounds__(256) void k_split_x(const float4* __restrict__ x) {
    const size_t idx = (size_t)blockIdx.x * 256 + threadIdx.x;
    float4 v = x[idx];
    __half2 h01, l01, h23, l23;
    split2(v.x, v.y, h01, l01);
    split2(v.z, v.w, h23, l23);
    __half2* ph = (__half2*)&g_xh[idx * 4];
    __half2* pl = (__half2*)&g_xl[idx * 4];
    ph[0] = h01; ph[1] = h23;
    pl[0] = l01; pl[1] = l23;
}

// ---------------------------------------------------------------------------
// k_wprep: u_i = W^T ai, u_j = W^T aj, c_i/c_j; W -> fp16 split. One CTA.
// ---------------------------------------------------------------------------
__global__ __launch_bounds__(256) void k_wprep(const float* __restrict__ W,
                                               const float* __restrict__ bW,
                                               const float* __restrict__ ai,
                                               const float* __restrict__ bi,
                                               const float* __restrict__ aj,
                                               const float* __restrict__ bj) {
    __shared__ float red[16];
    const int v = threadIdx.x;
    float ui = 0.f, uj = 0.f;
    for (int f = 0; f < FD; f++) {
        float w = W[f * VD + v];
        ui += ai[f] * w;
        uj += aj[f] * w;
    }
    g_ui[v] = ui;
    g_uj[v] = uj;

    for (int t = v; t < FD * VD / 2; t += 256) {
        float2 w2 = ((const float2*)W)[t];
        __half2 h, l;
        split2(w2.x, w2.y, h, l);
        *(__half2*)&g_W16h[2 * t] = h;
        *(__half2*)&g_W16l[2 * t] = l;
    }

    float p1 = ai[v] * bW[v];
    float p2 = aj[v] * bW[v];
    const int warp = v >> 5, lane = v & 31;
#pragma unroll
    for (int o = 16; o; o >>= 1) {
        p1 += __shfl_xor_sync(0xFFFFFFFFu, p1, o);
        p2 += __shfl_xor_sync(0xFFFFFFFFu, p2, o);
    }
    if (lane == 0) { red[warp] = p1; red[8 + warp] = p2; }
    __syncthreads();
    if (v == 0) {
        float c1 = bi[0], c2 = bj[0];
        for (int w = 0; w < 8; w++) { c1 += red[w]; c2 += red[8 + w]; }
        g_ci = c1; g_cj = c2;
    }
}

// ---------------------------------------------------------------------------
// k_projx: Wh1/Wh2 directly from x (warp per row)
// ---------------------------------------------------------------------------
__global__ __launch_bounds__(256) void k_projx(const float* __restrict__ x) {
    const int gwarp = (blockIdx.x * blockDim.x + threadIdx.x) >> 5;
    const int lane = threadIdx.x & 31;
    const float* row = x + (size_t)gwarp * VD;
    float s1 = 0.f, s2 = 0.f;
#pragma unroll
    for (int q = 0; q < 8; q++) {
        const int k = lane + 32 * q;
        float v = row[k];
        s1 += v * g_ui[k];
        s2 += v * g_uj[k];
    }
#pragma unroll
    for (int o = 16; o; o >>= 1) {
        s1 += __shfl_xor_sync(0xFFFFFFFFu, s1, o);
        s2 += __shfl_xor_sync(0xFFFFFFFFu, s2, o);
    }
    if (lane == 0) {
        g_Wh1[gwarp] = s1 + g_ci;
        g_Wh2[gwarp] = s2 + g_cj;
    }
}

// ---------------------------------------------------------------------------
// k_bm: adjacency -> bitmask (once; batch-independent). Warp per row.
// ---------------------------------------------------------------------------
__global__ __launch_bounds__(256) void k_bm(const int* __restrict__ adj) {
    const int row = blockIdx.x * 8 + (threadIdx.x >> 5);
    const int lane = threadIdx.x & 31;
    const int* ar = adj + (size_t)row * NODES;
    for (int w = 0; w < 50; w++) {
        uint32_t bit = __ballot_sync(0xFFFFFFFFu, ar[w * 32 + lane] > 0);
        if (lane == 0) g_bm[row * 50 + w] = bit;
    }
}

// ---------------------------------------------------------------------------
// k_g1mma: Wh = x @ W^T (+bW), 3-term fp16 hi/lo; epilogue -> WhT hi/lo.
// ---------------------------------------------------------------------------
__global__ __launch_bounds__(256) void k_g1mma(const float* __restrict__ bW) {
    extern __shared__ __align__(128) char dsm[];
    __shared__ float bWs[128];
    const int tid = threadIdx.x, wid = tid >> 5, lane = tid & 31;
    const int m0 = blockIdx.x * 64, n0 = blockIdx.y * 128;
    const int wm = wid >> 2, wn = wid & 3;

    if (tid < 128) bWs[tid] = bW[n0 + tid];

    const __half* Ah = g_xh + (size_t)m0 * VD;
    const __half* Al = g_xl + (size_t)m0 * VD;
    const __half* Bh = g_W16h + (size_t)n0 * VD;
    const __half* Bl = g_W16l + (size_t)n0 * VD;

    const uint32_t s0 = smem_u32(dsm);

    auto load_chunk = [&](int c) {
        const uint32_t st = s0 + (c & 1) * STAGE_G;
        const int jt = c * KCH;
        {
            int row = tid >> 2, cc = tid & 3;
            uint32_t o = (uint32_t)(row * 80 + cc * 16);
            const size_t go = (size_t)row * VD + jt + cc * 8;
            cp16(st + o,        Ah + go);
            cp16(st + 5120 + o, Al + go);
        }
        for (int t = tid; t < 512; t += 256) {
            int row = t >> 2, cc = t & 3;
            uint32_t o = (uint32_t)(row * 80 + cc * 16);
            const size_t go = (size_t)row * VD + jt + cc * 8;
            cp16(st + 10240 + o, Bh + go);
            cp16(st + 20480 + o, Bl + go);
        }
        CP_COMMIT();
    };

    float acc[2][4][4];
#pragma unroll
    for (int mt = 0; mt < 2; mt++)
#pragma unroll
        for (int nt = 0; nt < 4; nt++)
#pragma unroll
            for (int q = 0; q < 4; q++) acc[mt][nt][q] = 0.f;

    const int aRow = wm * 32 + (lane & 7) + ((lane >> 3) & 1) * 8;
    const int aC16 = ((lane >> 4) & 1) * 16;
    const int bRow = wn * 32 + (lane & 7) + ((lane >> 4) & 1) * 8;
    const int bC16 = ((lane >> 3) & 1) * 16;

    load_chunk(0);

    for (int c = 0; c < NCHG; c++) {
        if (c + 1 < NCHG) { load_chunk(c + 1); CP_WAIT1(); }
        else             { CP_WAIT0(); }
        __syncthreads();
        const uint32_t st = s0 + (c & 1) * STAGE_G;
#pragma unroll
        for (int ks = 0; ks < 2; ks++) {
            const int koff = ks * 32;
            uint32_t ah[2][4], al[2][4], bh[2][4], bl[2][4];
#pragma unroll
            for (int mt = 0; mt < 2; mt++) {
                uint32_t ao = st + (uint32_t)((aRow + mt * 16) * 80 + aC16 + koff);
                ldmx4(ah[mt], ao);
                ldmx4(al[mt], ao + 5120);
            }
#pragma unroll
            for (int p = 0; p < 2; p++) {
                uint32_t bo = st + 10240 +
                              (uint32_t)((bRow + p * 16) * 80 + bC16 + koff);
                ldmx4(bh[p], bo);
                ldmx4(bl[p], bo + 10240);
            }
#pragma unroll
            for (int mt = 0; mt < 2; mt++) {
#pragma unroll
                for (int nt = 0; nt < 4; nt++) {
                    const int p = nt >> 1, hf = (nt & 1) * 2;
                    mma16816(acc[mt][nt], ah[mt], bh[p][hf], bh[p][hf + 1]);
                    mma16816(acc[mt][nt], ah[mt], bl[p][hf], bl[p][hf + 1]);
                    mma16816(acc[mt][nt], al[mt], bh[p][hf], bh[p][hf + 1]);
                }
            }
        }
        __syncthreads();
    }

    float* s = (float*)dsm;   // [64][129]
#pragma unroll
    for (int mt = 0; mt < 2; mt++) {
        const int ml = wm * 32 + mt * 16 + (lane >> 2);
#pragma unroll
        for (int nt = 0; nt < 4; nt++) {
            const int nl = wn * 32 + nt * 8 + (lane & 3) * 2;
            s[ml * 129 + nl]           = acc[mt][nt][0];
            s[ml * 129 + nl + 1]       = acc[mt][nt][1];
            s[(ml + 8) * 129 + nl]     = acc[mt][nt][2];
            s[(ml + 8) * 129 + nl + 1] = acc[mt][nt][3];
        }
    }
    __syncthreads();

    const int b  = m0 / NODES;
    const int j0 = m0 % NODES;
#pragma unroll
    for (int it = 0; it < 16; it++) {
        const int f = wid * 16 + it;
        const float bw = bWs[f];
        float v0 = s[(2 * lane) * 129 + f] + bw;
        float v1 = s[(2 * lane + 1) * 129 + f] + bw;
        __half2 h, l;
        split2(v0, v1, h, l);
        size_t o = ((size_t)(b * FD + n0 + f)) * NODES + j0 + 2 * lane;
        *(__half2*)&g_WhT_hi[o] = h;
        *(__half2*)&g_WhT_lo[o] = l;
    }
}

// ---------------------------------------------------------------------------
// k_mma2f: FUSED masked-softmax + P @ Wh^T + deferred norm + ELU.
//   - prologue: per-row masked max from bm + Wh2 (monotonicity trick)
//   - per chunk: compute P tile (fp16, unnormalized exp) in smem, MMA it
//   - row sums via ones-operand MMA (fp32 exact); epilogue scales by 1/sum
// ---------------------------------------------------------------------------
__global__ __launch_bounds__(256) void k_mma2f(float* __restrict__ out) {
    extern __shared__ __align__(128) char dsm[];
    float*    Wh2s = (float*)dsm;                 // 1600
    float*    wh1s = Wh2s + NODES;                // 64
    float*    ms   = wh1s + 64;                   // 64
    uint32_t* bms  = (uint32_t*)(ms + 64);        // 64*50

    const int tid = threadIdx.x, wid = tid >> 5, lane = tid & 31;
    const int m0 = blockIdx.x * 64, n0 = blockIdx.y * 128, b = blockIdx.z;
    const int wm = wid >> 2, wn = wid & 3;

    const __half* Bh = g_WhT_hi + ((size_t)b * FD + n0) * NODES;
    const __half* Bl = g_WhT_lo + ((size_t)b * FD + n0) * NODES;

    const uint32_t s0 = smem_u32(dsm);
    const uint32_t sA = s0 + ABASE;
    const uint32_t sB = s0 + BBASE;

    auto loadB = [&](int c) {
        const uint32_t st = sB + (c & 1) * 20480;
        const int jt = c * KCH;
        for (int t = tid; t < 512; t += 256) {
            int row = t >> 2, cc = t & 3;
            uint32_t o = (uint32_t)(row * 80 + cc * 16);
            const size_t go = (size_t)row * NODES + jt + cc * 8;
            cp16(st + o,         Bh + go);
            cp16(st + 10240 + o, Bl + go);
        }
        CP_COMMIT();
    };

    loadB(0);

    // ---- fill smem: Wh2 row, Wh1 tile, bitmask rows ----
    for (int j = tid; j < NODES; j += 256)
        Wh2s[j] = g_Wh2[b * NODES + j];
    if (tid < 64)
        wh1s[tid] = g_Wh1[b * NODES + m0 + tid];
    for (int t = tid; t < 64 * 50; t += 256)
        bms[t] = g_bm[m0 * 50 + t];
    __syncthreads();

    // ---- prologue: masked max per row (warp wid -> rows wid*8..wid*8+7) ----
#pragma unroll
    for (int rr = 0; rr < 8; rr++) {
        const int r = wid * 8 + rr;
        const uint32_t* bmr = &bms[r * 50];
        float mx = -3e38f;
        for (int w = 0; w < 50; w++)
            if ((bmr[w] >> lane) & 1) mx = fmaxf(mx, Wh2s[w * 32 + lane]);
#pragma unroll
        for (int o = 16; o; o >>= 1) mx = fmaxf(mx, __shfl_xor_sync(0xFFFFFFFFu, mx, o));
        if (lane == 0) {
            float em = wh1s[r] + mx;
            em = em > 0.f ? em : 0.2f * em;
            ms[r] = (mx > -1e30f) ? em : -1e9f;
        }
    }
    __syncthreads();

    float acc[2][4][4];
    float accs[2][4];
#pragma unroll
    for (int mt = 0; mt < 2; mt++) {
#pragma unroll
        for (int nt = 0; nt < 4; nt++)
#pragma unroll
            for (int q = 0; q < 4; q++) acc[mt][nt][q] = 0.f;
#pragma unroll
        for (int q = 0; q < 4; q++) accs[mt][q] = 0.f;
    }

    const int aRow = wm * 32 + (lane & 7) + ((lane >> 3) & 1) * 8;
    const int aC16 = ((lane >> 4) & 1) * 16;
    const int bRow = wn * 32 + (lane & 7) + ((lane >> 4) & 1) * 8;
    const int bC16 = ((lane >> 3) & 1) * 16;
    const uint32_t ONES2 = 0x3C003C00u;  // half2(1.0, 1.0)

    // P-tile compute mapping: thread -> row pr (0..63), col group pq (0..3)
    const int pr = tid >> 2, pq = tid & 3;
    const float wh1r = wh1s[pr];
    const float mr   = ms[pr];
    const uint32_t* bmp = &bms[pr * 50];

    for (int c = 0; c < NCH; c++) {
        if (c + 1 < NCH) { loadB(c + 1); CP_WAIT1(); }
        else             { CP_WAIT0(); }

        // ---- compute A(c): P[pr][pq*8 .. pq*8+7] as fp16 ----
        {
            const int jt = c * KCH;
            const uint32_t word = bmp[c];          // KCH == 32: one word per chunk
            uint32_t uv[4];
#pragma unroll
            for (int u = 0; u < 4; u++) {
                const int jj = pq * 8 + u * 2;
                float2 w2 = *(const float2*)&Wh2s[jt + jj];
                float e0 = wh1r + w2.x; e0 = e0 > 0.f ? e0 : 0.2f * e0;
                float e1 = wh1r + w2.y; e1 = e1 > 0.f ? e1 : 0.2f * e1;
                float x0 = __expf((((word >> jj) & 1)       ? e0 : -1e9f) - mr);
                float x1 = __expf((((word >> (jj + 1)) & 1) ? e1 : -1e9f) - mr);
                __half2 hh = __halves2half2(__float2half_rn(x0), __float2half_rn(x1));
                uv[u] = *(uint32_t*)&hh;
            }
            *(uint4*)(dsm + ABASE + (c & 1) * 5120 + pr * 80 + pq * 16) =
                make_uint4(uv[0], uv[1], uv[2], uv[3]);
        }
        __syncthreads();

        const uint32_t stA = sA + (c & 1) * 5120;
        const uint32_t stB = sB + (c & 1) * 20480;
#pragma unroll
        for (int ks = 0; ks < 2; ks++) {
            const int koff = ks * 32;
            uint32_t ah[2][4], bh[2][4], bl[2][4];
#pragma unroll
            for (int mt = 0; mt < 2; mt++) {
                uint32_t ao = stA + (uint32_t)((aRow + mt * 16) * 80 + aC16 + koff);
                ldmx4(ah[mt], ao);
            }
#pragma unroll
            for (int p = 0; p < 2; p++) {
                uint32_t bo = stB + (uint32_t)((bRow + p * 16) * 80 + bC16 + koff);
                ldmx4(bh[p], bo);
                ldmx4(bl[p], bo + 10240);
            }
#pragma unroll
            for (int mt = 0; mt < 2; mt++) {
#pragma unroll
                for (int nt = 0; nt < 4; nt++) {
                    const int p = nt >> 1, hf = (nt & 1) * 2;
                    mma16816(acc[mt][nt], ah[mt], bh[p][hf], bh[p][hf + 1]);
                    mma16816(acc[mt][nt], ah[mt], bl[p][hf], bl[p][hf + 1]);
                }
                mma16816(accs[mt], ah[mt], ONES2, ONES2);  // row sums
            }
        }
        __syncthreads();
    }

    // ---- epilogue: scale by 1/rowsum, ELU, store ----
#pragma unroll
    for (int mt = 0; mt < 2; mt++) {
        const int mA = m0 + wm * 32 + mt * 16 + (lane >> 2);
        const float ilA = 1.f / accs[mt][0];
        const float ilB = 1.f / accs[mt][2];
#pragma unroll
        for (int nt = 0; nt < 4; nt++) {
            const int n = n0 + wn * 32 + nt * 8 + (lane & 3) * 2;
            float* op = out + ((size_t)(b * NODES) + mA) * FD + n;
            float d0 = acc[mt][nt][0] * ilA, d1 = acc[mt][nt][1] * ilA;
            float d2 = acc[mt][nt][2] * ilB, d3 = acc[mt][nt][3] * ilB;
            float2 v0, v1;
            v0.x = d0 > 0.f ? d0 : (__expf(d0) - 1.f);
            v0.y = d1 > 0.f ? d1 : (__expf(d1) - 1.f);
            v1.x = d2 > 0.f ? d2 : (__expf(d2) - 1.f);
            v1.y = d3 > 0.f ? d3 : (__expf(d3) - 1.f);
            *(float2*)op = v0;
            *(float2*)(op + 8 * FD) = v1;
        }
    }
}

// ---------------------------------------------------------------------------
extern "C" void kernel_launch(void* const* d_in, const int* in_sizes, int n_in,
                              void* d_out, int out_size) {
    const float* h   = (const float*)d_in[0];
    const int*   adj = (const int*)  d_in[1];
    const float* W   = (const float*)d_in[2];
    const float* bW  = (const float*)d_in[3];
    const float* ai  = (const float*)d_in[4];
    const float* bi  = (const float*)d_in[5];
    const float* aj  = (const float*)d_in[6];
    const float* bj  = (const float*)d_in[7];
    float* out = (float*)d_out;

    cudaFuncSetAttribute(k_g1mma, cudaFuncAttributeMaxDynamicSharedMemorySize, SMEM_G);
    cudaFuncSetAttribute(k_mma2f, cudaFuncAttributeMaxDynamicSharedMemorySize, SMEM_M);

    k_split_x<<<(MTOT * VD / 4) / 256, 256>>>((const float4*)h);
    k_wprep<<<1, 256>>>(W, bW, ai, bi, aj, bj);
    k_projx<<<MTOT / 8, 256>>>(h);
    k_bm<<<NODES / 8, 256>>>(adj);
    k_g1mma<<<dim3(MTOT / 64, 2), 256, SMEM_G>>>(bW);
    dim3 gm(NODES / 64, FD / 128, BB);
    k_mma2f<<<gm, 256, SMEM_M>>>(out);
}